// round 5
// baseline (speedup 1.0000x reference)
#include <cuda_runtime.h>
#include <cuda_bf16.h>
#include <mma.h>
#include <math.h>
#include <stdint.h>

using namespace nvcuda;

// ---------------- problem constants ----------------
#define Bz   2048
#define Tz   71
#define Dz   1024
#define Hz   8
#define DHz  128
#define Lz   12
#define NTOK (Bz*Tz)            // 145408
#define MTILES (NTOK/128)       // 1136

// ---------------- device scratch ----------------
__device__ float g_x [NTOK*Dz];     // fp32 residual stream
__device__ float g_xr[NTOK*Dz];     // tf32-rounded copy of x (GEMM A operand)
__device__ float g_q [NTOK*Dz];
__device__ float g_k [NTOK*Dz];
__device__ float g_v [NTOK*Dz];
__device__ float g_y1[NTOK*Dz];     // ff1 out (tf32-rounded; only feeds ff2 GEMM)
__device__ float g_t [Bz*2*Dz];     // head tokens, tf32-rounded
__device__ float g_h1[Bz*2*Dz];
__device__ float g_qkvT[Lz*3*Hz*DHz*DHz];   // tf32-rounded, K-contiguous
__device__ float g_ff1T[Lz*Hz*DHz*Dz];
__device__ float g_ff2T[Lz*Hz*DHz*DHz];
__device__ float g_w1r[2*Dz*2*Dz];          // W1 tf32-rounded (rows already K-contig)

__device__ __forceinline__ float lrelu(float x) { return x > 0.f ? x : 0.2f * x; }
__device__ __forceinline__ float tfr(float x) { return wmma::__float_to_tf32(x); }

// ---------------- cp.async helpers ----------------
__device__ __forceinline__ void cpa16(uint32_t s, const float* g) {
    asm volatile("cp.async.cg.shared.global [%0], [%1], 16;" :: "r"(s), "l"(g));
}
#define CPA_COMMIT() asm volatile("cp.async.commit_group;" ::: "memory")
#define CPA_WAIT1()  asm volatile("cp.async.wait_group 1;" ::: "memory")
#define CPA_WAIT0()  asm volatile("cp.async.wait_group 0;" ::: "memory")

// ---------------- wmma tf32 GEMM core: CTA 128x128, 8 warps (4m x 2n) ----------------
using FragA = wmma::fragment<wmma::matrix_a, 16, 16, 8, wmma::precision::tf32, wmma::row_major>;
using FragB = wmma::fragment<wmma::matrix_b, 16, 16, 8, wmma::precision::tf32, wmma::col_major>;
using FragC = wmma::fragment<wmma::accumulator, 16, 16, 8, float>;

#define LDS 36                           // smem row stride (floats); 144B = 16B-aligned
#define MBUF (128 * LDS)                 // floats per matrix buffer
#define GSM  (4 * MBUF * 4)              // dynamic smem bytes (2 stages x (A+B))

// A: row-major [128 x K] (lda), B: K-contiguous [128n x K] (ldb) => C = A @ B^T
// Inputs must already be tf32-rounded (HW truncation then exact).
__device__ __forceinline__ void gemm_async(const float* __restrict__ A, int lda,
                                           const float* __restrict__ B, int ldb,
                                           int K, FragC (&acc)[2][4], float* sm)
{
    const int tid = threadIdx.x;
    const int warp = tid >> 5;
    const int wm = warp & 3;
    const int wn = warp >> 2;
    const uint32_t smu = (uint32_t)__cvta_generic_to_shared(sm);

#pragma unroll
    for (int i = 0; i < 2; ++i)
#pragma unroll
        for (int j = 0; j < 4; ++j)
            wmma::fill_fragment(acc[i][j], 0.f);

    const int row = tid >> 1;                 // 0..127
    const int sg0 = (tid & 1) << 2;           // 0 or 4 (two 16B segs per half)
    const int nch = K / 32;

    auto issue = [&](int c, int buf) {
        const int kk = c * 32;
        const uint32_t base = smu + (uint32_t)buf * 2u * MBUF * 4u;
        const float* Ap = A + (size_t)row * lda + kk + sg0 * 4;
        const float* Bp = B + (size_t)row * ldb + kk + sg0 * 4;
        uint32_t sA = base + (uint32_t)(row * LDS + sg0 * 4) * 4u;
        uint32_t sB = sA + (uint32_t)MBUF * 4u;
        cpa16(sA,      Ap);
        cpa16(sA + 16, Ap + 4);
        cpa16(sA + 32, Ap + 8);
        cpa16(sA + 48, Ap + 12);
        cpa16(sB,      Bp);
        cpa16(sB + 16, Bp + 4);
        cpa16(sB + 32, Bp + 8);
        cpa16(sB + 48, Bp + 12);
        CPA_COMMIT();
    };

    issue(0, 0);
    for (int c = 0; c < nch; ++c) {
        if (c + 1 < nch) { issue(c + 1, (c + 1) & 1); CPA_WAIT1(); }
        else             { CPA_WAIT0(); }
        __syncthreads();
        float* As = sm + (c & 1) * 2 * MBUF;
        float* Bs = As + MBUF;
#pragma unroll
        for (int ks = 0; ks < 4; ++ks) {
            FragA af[2];
            wmma::load_matrix_sync(af[0], As + (wm * 32) * LDS + ks * 8, LDS);
            wmma::load_matrix_sync(af[1], As + (wm * 32 + 16) * LDS + ks * 8, LDS);
#pragma unroll
            for (int j = 0; j < 4; ++j) {
                FragB bf;
                wmma::load_matrix_sync(bf, Bs + (wn * 64 + j * 16) * LDS + ks * 8, LDS);
                wmma::mma_sync(acc[0][j], af[0], bf, acc[0][j]);
                wmma::mma_sync(acc[1][j], af[1], bf, acc[1][j]);
            }
        }
        __syncthreads();
    }
}

// ---------------- GEMM kernels ----------------
__global__ void __launch_bounds__(256, 2) qkv_tc(const float* __restrict__ qkvT_l)
{
    extern __shared__ float sm[];
    int sh = blockIdx.x, s = sh >> 3, h = sh & 7;
    int m0 = blockIdx.y * 128;
    FragC acc[2][4];
    gemm_async(g_xr + (size_t)m0 * Dz + h * DHz, Dz,
               qkvT_l + (size_t)sh * (DHz * DHz), DHz, DHz, acc, sm);

    float* out = (s == 0) ? g_q : (s == 1) ? g_k : g_v;
    int wm = (threadIdx.x >> 5) & 3, wn = threadIdx.x >> 7;
#pragma unroll
    for (int i = 0; i < 2; ++i)
#pragma unroll
        for (int j = 0; j < 4; ++j)
            wmma::store_matrix_sync(out + (size_t)(m0 + wm * 32 + i * 16) * Dz
                                        + h * DHz + wn * 64 + j * 16,
                                    acc[i][j], Dz, wmma::mem_row_major);
}

__global__ void __launch_bounds__(256, 2) ff1_tc(const float* __restrict__ ff1T_l)
{
    extern __shared__ float sm[];
    int n0 = blockIdx.x * 128, m0 = blockIdx.y * 128;
    FragC acc[2][4];
    gemm_async(g_xr + (size_t)m0 * Dz, Dz,
               ff1T_l + (size_t)n0 * Dz, Dz, Dz, acc, sm);

    int wm = (threadIdx.x >> 5) & 3, wn = threadIdx.x >> 7;
#pragma unroll
    for (int i = 0; i < 2; ++i)
#pragma unroll
        for (int j = 0; j < 4; ++j) {
#pragma unroll
            for (int e = 0; e < acc[i][j].num_elements; ++e)
                acc[i][j].x[e] = tfr(lrelu(acc[i][j].x[e]));   // rounded: feeds ff2 GEMM
            wmma::store_matrix_sync(g_y1 + (size_t)(m0 + wm * 32 + i * 16) * Dz
                                         + n0 + wn * 64 + j * 16,
                                    acc[i][j], Dz, wmma::mem_row_major);
        }
}

__global__ void __launch_bounds__(256, 2) ff2_tc(const float* __restrict__ ff2T_l)
{
    extern __shared__ float sm[];
    int h = blockIdx.x, m0 = blockIdx.y * 128;
    FragC acc[2][4];
    gemm_async(g_y1 + (size_t)m0 * Dz + h * DHz, Dz,
               ff2T_l + (size_t)h * (DHz * DHz), DHz, DHz, acc, sm);

    int wm = (threadIdx.x >> 5) & 3, wn = threadIdx.x >> 7;
#pragma unroll
    for (int i = 0; i < 2; ++i)
#pragma unroll
        for (int j = 0; j < 4; ++j) {
            size_t off = (size_t)(m0 + wm * 32 + i * 16) * Dz + h * DHz + wn * 64 + j * 16;
            FragC c;
            wmma::load_matrix_sync(c, g_x + off, Dz, wmma::mem_row_major);
#pragma unroll
            for (int e = 0; e < c.num_elements; ++e)
                c.x[e] += lrelu(acc[i][j].x[e]);
            wmma::store_matrix_sync(g_x + off, c, Dz, wmma::mem_row_major);
#pragma unroll
            for (int e = 0; e < c.num_elements; ++e)
                c.x[e] = tfr(c.x[e]);
            wmma::store_matrix_sync(g_xr + off, c, Dz, wmma::mem_row_major);
        }
}

__global__ void __launch_bounds__(256, 2) head_tc()
{
    extern __shared__ float sm[];
    int n0 = blockIdx.x * 128, m0 = blockIdx.y * 128;
    FragC acc[2][4];
    gemm_async(g_t + (size_t)m0 * 2048, 2048,
               g_w1r + (size_t)n0 * 2048, 2048, 2048, acc, sm);

    int wm = (threadIdx.x >> 5) & 3, wn = threadIdx.x >> 7;
#pragma unroll
    for (int i = 0; i < 2; ++i)
#pragma unroll
        for (int j = 0; j < 4; ++j)
            wmma::store_matrix_sync(g_h1 + (size_t)(m0 + wm * 32 + i * 16) * 2048
                                         + n0 + wn * 64 + j * 16,
                                    acc[i][j], 2048, wmma::mem_row_major);
}

__global__ void __launch_bounds__(512) head_bias(const float* __restrict__ b1)
{
    int idx = blockIdx.x * 512 + threadIdx.x;
    g_h1[idx] = lrelu(g_h1[idx] + b1[idx & 2047]);
}

// ---------------- embedding + layernorm ----------------
__device__ __forceinline__ void blockReduce2(float& s1, float& s2) {
    __shared__ float buf[32];
    int lane = threadIdx.x & 31, warp = threadIdx.x >> 5;
#pragma unroll
    for (int o = 16; o; o >>= 1) {
        s1 += __shfl_xor_sync(0xffffffffu, s1, o);
        s2 += __shfl_xor_sync(0xffffffffu, s2, o);
    }
    if (lane == 0) { buf[warp] = s1; buf[16 + warp] = s2; }
    __syncthreads();
    float t1 = 0.f, t2 = 0.f;
#pragma unroll
    for (int w = 0; w < 8; ++w) { t1 += buf[w]; t2 += buf[16 + w]; }
    s1 = t1; s2 = t2;
}

__global__ void __launch_bounds__(256) embed_kernel(
    const int* __restrict__ fen, const int* __restrict__ move,
    const float* __restrict__ rank_emb, const float* __restrict__ file_emb,
    const float* __restrict__ fen_emb, const float* __restrict__ move_emb,
    const float* __restrict__ lng, const float* __restrict__ lnb,
    const float* __restrict__ abs_emb)
{
    int token = blockIdx.x;
    int b = token / Tz, t = token - b * Tz;
    int tid = threadIdx.x;
    float vals[4];

    if (t < 64) {
        int i1 = fen[b * 133 + t];
        int i2 = fen[b * 133 + 64 + t];
        int r = t >> 3, f = t & 7;
#pragma unroll
        for (int c = 0; c < 4; ++c) {
            int d = tid + c * 256;
            vals[c] = 0.5f * (fen_emb[i1 * Dz + d] + fen_emb[i2 * Dz + d]
                              + rank_emb[r * Dz + d] + file_emb[f * Dz + d])
                      + abs_emb[t * Dz + d];
        }
    } else if (t < 69) {
        int i1 = fen[b * 133 + 128 + (t - 64)];
#pragma unroll
        for (int c = 0; c < 4; ++c) {
            int d = tid + c * 256;
            vals[c] = fen_emb[i1 * Dz + d] + abs_emb[t * Dz + d];
        }
    } else {
        int i = t - 69;
        int m = move[b * 2 + i];
        int r = m >> 3, f = m & 7;
#pragma unroll
        for (int c = 0; c < 4; ++c) {
            int d = tid + c * 256;
            vals[c] = (rank_emb[r * Dz + d] + file_emb[f * Dz + d] + move_emb[i * Dz + d]) * 0.58f
                      + abs_emb[t * Dz + d];
        }
    }

    float s1 = 0.f, s2 = 0.f;
#pragma unroll
    for (int c = 0; c < 4; ++c) { s1 += vals[c]; s2 += vals[c] * vals[c]; }
    blockReduce2(s1, s2);
    float mean = s1 * (1.f / 1024.f);
    float var  = s2 * (1.f / 1024.f) - mean * mean;
    float inv  = rsqrtf(var + 1e-5f);

    float* xp  = g_x  + (size_t)token * Dz;
    float* xrp = g_xr + (size_t)token * Dz;
#pragma unroll
    for (int c = 0; c < 4; ++c) {
        int d = tid + c * 256;
        float y = (vals[c] - mean) * inv * lng[d] + lnb[d];
        xp[d]  = y;
        xrp[d] = tfr(y);
    }
}

// ---------------- weight prep ----------------
__global__ void transposeW(const float* __restrict__ src, float* __restrict__ dst, int K)
{
    __shared__ float tile[32][33];
    size_t mstride = (size_t)K * 128;
    src += blockIdx.z * mstride;
    dst += blockIdx.z * mstride;
    int k0 = blockIdx.x * 32, n0 = blockIdx.y * 32;
    for (int i = threadIdx.y; i < 32; i += 8)
        tile[i][threadIdx.x] = src[(size_t)(k0 + i) * 128 + n0 + threadIdx.x];
    __syncthreads();
    for (int i = threadIdx.y; i < 32; i += 8)
        dst[(size_t)(n0 + i) * K + k0 + threadIdx.x] = tfr(tile[threadIdx.x][i]);
}

__global__ void __launch_bounds__(512) roundW1(const float* __restrict__ W1)
{
    int idx = blockIdx.x * 512 + threadIdx.x;
    g_w1r[idx] = tfr(W1[idx]);
}

// ---------------- attention (SIMT) ----------------
__global__ void __launch_bounds__(256) attn_kernel()
{
    int b = blockIdx.x, h = blockIdx.y;
    int tid = threadIdx.x;
    extern __shared__ float smf[];
    float* qs = smf;
    float* ks = qs + Tz * 128;
    float* vs = ks + Tz * 129;
    float* ps = vs + Tz * 128;

    const float* qb = g_q + ((size_t)b * Tz) * Dz + h * DHz;
    const float* kb = g_k + ((size_t)b * Tz) * Dz + h * DHz;
    const float* vb = g_v + ((size_t)b * Tz) * Dz + h * DHz;

    for (int i = tid; i < Tz * 128; i += 256) {
        int t = i >> 7, d = i & 127;
        qs[t * 128 + d] = qb[(size_t)t * Dz + d];
        ks[t * 129 + d] = kb[(size_t)t * Dz + d];
        vs[t * 128 + d] = vb[(size_t)t * Dz + d];
    }
    __syncthreads();

    const float inv_scale = 0.08838834764831845f;
    for (int idx = tid; idx < Tz * Tz; idx += 256) {
        int i = idx / Tz, j = idx - i * Tz;
        float s = 0.f;
#pragma unroll 8
        for (int dd = 0; dd < 128; ++dd)
            s = fmaf(qs[i * 128 + dd], ks[j * 129 + dd], s);
        ps[i * 72 + j] = s * inv_scale;
    }
    __syncthreads();

    int warp = tid >> 5, lane = tid & 31;
    for (int r = warp; r < Tz; r += 8) {
        float m = -1e30f;
        for (int j = lane; j < Tz; j += 32) m = fmaxf(m, ps[r * 72 + j]);
#pragma unroll
        for (int o = 16; o; o >>= 1) m = fmaxf(m, __shfl_xor_sync(0xffffffffu, m, o));
        float ssum = 0.f;
        for (int j = lane; j < Tz; j += 32) {
            float e = expf(ps[r * 72 + j] - m);
            ps[r * 72 + j] = e;
            ssum += e;
        }
#pragma unroll
        for (int o = 16; o; o >>= 1) ssum += __shfl_xor_sync(0xffffffffu, ssum, o);
        float inv = 1.f / ssum;
        for (int j = lane; j < Tz; j += 32) ps[r * 72 + j] *= inv;
    }
    __syncthreads();

    float* xb  = g_x  + ((size_t)b * Tz) * Dz + h * DHz;
    float* xrb = g_xr + ((size_t)b * Tz) * Dz + h * DHz;
    for (int idx = tid; idx < Tz * 128; idx += 256) {
        int i = idx >> 7, d = idx & 127;
        float a = 0.f;
#pragma unroll 8
        for (int j = 0; j < Tz; ++j)
            a = fmaf(ps[i * 72 + j], vs[j * 128 + d], a);
        float y = xb[(size_t)i * Dz + d] + a;
        xb[(size_t)i * Dz + d]  = y;
        xrb[(size_t)i * Dz + d] = tfr(y);
    }
}

// ---------------- head: gather + LN over 2048 ----------------
__global__ void __launch_bounds__(256) gather_ln_kernel(const float* __restrict__ g,
                                                        const float* __restrict__ bb)
{
    int b = blockIdx.x, tid = threadIdx.x;
    const float* x69 = g_x + ((size_t)b * Tz + 69) * Dz;
    float vals[8];
#pragma unroll
    for (int c = 0; c < 8; ++c) vals[c] = x69[tid + c * 256];
    float s1 = 0.f, s2 = 0.f;
#pragma unroll
    for (int c = 0; c < 8; ++c) { s1 += vals[c]; s2 += vals[c] * vals[c]; }
    blockReduce2(s1, s2);
    float mean = s1 * (1.f / 2048.f);
    float var  = s2 * (1.f / 2048.f) - mean * mean;
    float inv  = rsqrtf(var + 1e-5f);
    float* tp = g_t + (size_t)b * 2048;
#pragma unroll
    for (int c = 0; c < 8; ++c) {
        int k = tid + c * 256;
        tp[k] = tfr((vals[c] - mean) * inv * g[k] + bb[k]);
    }
}

__global__ void __launch_bounds__(256) final_kernel(const float* __restrict__ W2,
                                                    const float* __restrict__ b2,
                                                    float* __restrict__ out)
{
    int b = blockIdx.x, tid = threadIdx.x;
    const float* hp = g_h1 + (size_t)b * 2048;
    float s = 0.f;
    for (int k = tid; k < 2048; k += 256) s = fmaf(hp[k], W2[k], s);
    float dummy = 0.f;
    blockReduce2(s, dummy);
    if (tid == 0) out[b] = 1.f / (1.f + expf(-(s + b2[0])));
}

// ---------------- launch ----------------
extern "C" void kernel_launch(void* const* d_in, const int* in_sizes, int n_in,
                              void* d_out, int out_size)
{
    const int*   fen      = (const int*)  d_in[0];
    const int*   move     = (const int*)  d_in[1];
    const float* rank_emb = (const float*)d_in[2];
    const float* file_emb = (const float*)d_in[3];
    const float* fen_emb  = (const float*)d_in[4];
    const float* move_emb = (const float*)d_in[5];
    const float* ln_emb_g = (const float*)d_in[6];
    const float* ln_emb_b = (const float*)d_in[7];
    const float* abs_emb  = (const float*)d_in[8];
    const float* qkvw     = (const float*)d_in[9];
    const float* ff1w     = (const float*)d_in[10];
    const float* ff2w     = (const float*)d_in[11];
    const float* ln_out_g = (const float*)d_in[12];
    const float* ln_out_b = (const float*)d_in[13];
    const float* W1       = (const float*)d_in[14];
    const float* b1       = (const float*)d_in[15];
    const float* W2       = (const float*)d_in[16];
    const float* b2       = (const float*)d_in[17];
    float* out = (float*)d_out;

    const int ATTN_SMEM = (Tz * 128 * 2 + Tz * 129 + Tz * 72) * (int)sizeof(float);
    cudaFuncSetAttribute(attn_kernel, cudaFuncAttributeMaxDynamicSharedMemorySize, ATTN_SMEM);
    cudaFuncSetAttribute(qkv_tc,  cudaFuncAttributeMaxDynamicSharedMemorySize, GSM);
    cudaFuncSetAttribute(ff1_tc,  cudaFuncAttributeMaxDynamicSharedMemorySize, GSM);
    cudaFuncSetAttribute(ff2_tc,  cudaFuncAttributeMaxDynamicSharedMemorySize, GSM);
    cudaFuncSetAttribute(head_tc, cudaFuncAttributeMaxDynamicSharedMemorySize, GSM);

    float* qkvT; cudaGetSymbolAddress((void**)&qkvT, g_qkvT);
    float* ff1T; cudaGetSymbolAddress((void**)&ff1T, g_ff1T);
    float* ff2T; cudaGetSymbolAddress((void**)&ff2T, g_ff2T);
    transposeW<<<dim3(4, 4, Lz * 3 * Hz), dim3(32, 8)>>>(qkvw, qkvT, 128);
    transposeW<<<dim3(32, 4, Lz * Hz), dim3(32, 8)>>>(ff1w, ff1T, 1024);
    transposeW<<<dim3(4, 4, Lz * Hz), dim3(32, 8)>>>(ff2w, ff2T, 128);
    roundW1<<<(2 * Dz * 2 * Dz) / 512, 512>>>(W1);

    embed_kernel<<<NTOK, 256>>>(fen, move, rank_emb, file_emb, fen_emb, move_emb,
                                ln_emb_g, ln_emb_b, abs_emb);

    for (int l = 0; l < Lz; ++l) {
        const float* qkvT_l = qkvT + (size_t)l * 3 * Hz * DHz * DHz;
        const float* ff1T_l = ff1T + (size_t)l * Hz * DHz * Dz;
        const float* ff2T_l = ff2T + (size_t)l * Hz * DHz * DHz;
        qkv_tc<<<dim3(24, MTILES), 256, GSM>>>(qkvT_l);
        attn_kernel<<<dim3(Bz, Hz), 256, ATTN_SMEM>>>();
        ff1_tc<<<dim3(8, MTILES), 256, GSM>>>(ff1T_l);
        ff2_tc<<<dim3(8, MTILES), 256, GSM>>>(ff2T_l);
    }

    gather_ln_kernel<<<Bz, 256>>>(ln_out_g, ln_out_b);
    head_tc<<<dim3(16, 16), 256, GSM>>>();
    head_bias<<<(Bz * 2048) / 512, 512>>>(b1);
    final_kernel<<<Bz, 256>>>(W2, b2, out);
}

// round 6
// speedup vs baseline: 1.5694x; 1.5694x over previous
#include <cuda_runtime.h>
#include <cuda_fp16.h>
#include <mma.h>
#include <math.h>
#include <stdint.h>

using namespace nvcuda;

// ---------------- problem constants ----------------
#define Bz   2048
#define Tz   71
#define Dz   1024
#define Hz   8
#define DHz  128
#define Lz   12
#define NTOK (Bz*Tz)            // 145408
#define MTILES (NTOK/128)       // 1136

// ---------------- device scratch ----------------
__device__ float  g_x  [NTOK*Dz];   // fp32 residual stream
__device__ __half g_xh [NTOK*Dz];   // half copy (GEMM A operand)
__device__ float  g_q  [NTOK*Dz];
__device__ float  g_k  [NTOK*Dz];
__device__ float  g_v  [NTOK*Dz];
__device__ float  g_y1 [NTOK*Dz];   // ff1 raw out (fp32 staging)
__device__ __half g_y1h[NTOK*Dz];   // lrelu(y1) in half (ff2 A operand)
__device__ __half g_th [Bz*2*Dz];   // head tokens (half)
__device__ float  g_h1 [Bz*2*Dz];
__device__ __half g_qkvTh[Lz*3*Hz*DHz*DHz];  // K-contiguous half weights
__device__ __half g_ff1Th[Lz*Hz*DHz*Dz];
__device__ __half g_ff2Th[Lz*Hz*DHz*DHz];
__device__ __half g_w1h[2*Dz*2*Dz];

__device__ __forceinline__ float lrelu(float x) { return x > 0.f ? x : 0.2f * x; }

// ---------------- cp.async helpers ----------------
__device__ __forceinline__ void cpa16(uint32_t s, const void* g) {
    asm volatile("cp.async.cg.shared.global [%0], [%1], 16;" :: "r"(s), "l"(g));
}
#define CPA_COMMIT() asm volatile("cp.async.commit_group;" ::: "memory")
#define CPA_WAIT1()  asm volatile("cp.async.wait_group 1;" ::: "memory")
#define CPA_WAIT0()  asm volatile("cp.async.wait_group 0;" ::: "memory")

// ---------------- wmma fp16 GEMM core: CTA 128x128, 8 warps (4m x 2n), K-chunk 64 ----------------
using FragA = wmma::fragment<wmma::matrix_a, 16, 16, 16, __half, wmma::row_major>;
using FragB = wmma::fragment<wmma::matrix_b, 16, 16, 16, __half, wmma::col_major>;
using FragC = wmma::fragment<wmma::accumulator, 16, 16, 16, float>;

#define LDSH  72                     // smem row stride in halfs (144B; conflict-free, 16B-mult)
#define MBUFH (128 * LDSH)           // halfs per matrix buffer
#define GSMH  (2 * 2 * MBUFH * 2)    // bytes: 2 stages x (A+B) = 73728

// A: row-major [128 x K] half (lda), B: K-contiguous [128n x K] half (ldb) => C = A @ B^T
__device__ __forceinline__ void gemm_h(const __half* __restrict__ A, int lda,
                                       const __half* __restrict__ B, int ldb,
                                       int K, FragC (&acc)[2][4], __half* sm)
{
    const int tid = threadIdx.x;
    const int warp = tid >> 5;
    const int wm = warp & 3;
    const int wn = warp >> 2;
    const uint32_t smu = (uint32_t)__cvta_generic_to_shared(sm);

#pragma unroll
    for (int i = 0; i < 2; ++i)
#pragma unroll
        for (int j = 0; j < 4; ++j)
            wmma::fill_fragment(acc[i][j], 0.f);

    const int nch = K / 64;

    auto issue = [&](int c, int buf) {
        const int kk = c * 64;
        const uint32_t base = smu + (uint32_t)buf * (2u * MBUFH * 2u);
#pragma unroll
        for (int it = 0; it < 4; ++it) {            // A: 128 rows x 8 segs of 16B
            int idx = tid + it * 256;
            int row = idx >> 3, seg = idx & 7;
            cpa16(base + (uint32_t)(row * LDSH * 2 + seg * 16),
                  A + (size_t)row * lda + kk + seg * 8);
        }
#pragma unroll
        for (int it = 0; it < 4; ++it) {            // B
            int idx = tid + it * 256;
            int row = idx >> 3, seg = idx & 7;
            cpa16(base + (uint32_t)(MBUFH * 2) + (uint32_t)(row * LDSH * 2 + seg * 16),
                  B + (size_t)row * ldb + kk + seg * 8);
        }
        CPA_COMMIT();
    };

    issue(0, 0);
    for (int c = 0; c < nch; ++c) {
        if (c + 1 < nch) { issue(c + 1, (c + 1) & 1); CPA_WAIT1(); }
        else             { CPA_WAIT0(); }
        __syncthreads();
        __half* As = sm + (c & 1) * 2 * MBUFH;
        __half* Bs = As + MBUFH;
#pragma unroll
        for (int ks = 0; ks < 4; ++ks) {
            FragA af[2];
            wmma::load_matrix_sync(af[0], As + (wm * 32) * LDSH + ks * 16, LDSH);
            wmma::load_matrix_sync(af[1], As + (wm * 32 + 16) * LDSH + ks * 16, LDSH);
#pragma unroll
            for (int j = 0; j < 4; ++j) {
                FragB bf;
                wmma::load_matrix_sync(bf, Bs + (wn * 64 + j * 16) * LDSH + ks * 16, LDSH);
                wmma::mma_sync(acc[0][j], af[0], bf, acc[0][j]);
                wmma::mma_sync(acc[1][j], af[1], bf, acc[1][j]);
            }
        }
        __syncthreads();
    }
}

// ---------------- GEMM kernels ----------------
__global__ void __launch_bounds__(256, 2) qkv_tc(const __half* __restrict__ qkvT_l)
{
    extern __shared__ __align__(128) __half smh[];
    int sh = blockIdx.x, s = sh >> 3, h = sh & 7;
    int m0 = blockIdx.y * 128;
    FragC acc[2][4];
    gemm_h(g_xh + (size_t)m0 * Dz + h * DHz, Dz,
           qkvT_l + (size_t)sh * (DHz * DHz), DHz, DHz, acc, smh);

    float* out = (s == 0) ? g_q : (s == 1) ? g_k : g_v;
    int wm = (threadIdx.x >> 5) & 3, wn = threadIdx.x >> 7;
#pragma unroll
    for (int i = 0; i < 2; ++i)
#pragma unroll
        for (int j = 0; j < 4; ++j)
            wmma::store_matrix_sync(out + (size_t)(m0 + wm * 32 + i * 16) * Dz
                                        + h * DHz + wn * 64 + j * 16,
                                    acc[i][j], Dz, wmma::mem_row_major);
}

__global__ void __launch_bounds__(256, 2) ff1_tc(const __half* __restrict__ ff1T_l)
{
    extern __shared__ __align__(128) __half smh[];
    int n0 = blockIdx.x * 128, m0 = blockIdx.y * 128;
    FragC acc[2][4];
    gemm_h(g_xh + (size_t)m0 * Dz, Dz,
           ff1T_l + (size_t)n0 * Dz, Dz, Dz, acc, smh);

    int wm = (threadIdx.x >> 5) & 3, wn = threadIdx.x >> 7;
#pragma unroll
    for (int i = 0; i < 2; ++i)
#pragma unroll
        for (int j = 0; j < 4; ++j)
            wmma::store_matrix_sync(g_y1 + (size_t)(m0 + wm * 32 + i * 16) * Dz
                                         + n0 + wn * 64 + j * 16,
                                    acc[i][j], Dz, wmma::mem_row_major);
}

__global__ void __launch_bounds__(256, 2) ff2_tc(const __half* __restrict__ ff2T_l)
{
    extern __shared__ __align__(128) __half smh[];
    int h = blockIdx.x, m0 = blockIdx.y * 128;
    FragC acc[2][4];
    gemm_h(g_y1h + (size_t)m0 * Dz + h * DHz, Dz,
           ff2T_l + (size_t)h * (DHz * DHz), DHz, DHz, acc, smh);

    int wm = (threadIdx.x >> 5) & 3, wn = threadIdx.x >> 7;
#pragma unroll
    for (int i = 0; i < 2; ++i)
#pragma unroll
        for (int j = 0; j < 4; ++j) {
            size_t off = (size_t)(m0 + wm * 32 + i * 16) * Dz + h * DHz + wn * 64 + j * 16;
            FragC c;
            wmma::load_matrix_sync(c, g_x + off, Dz, wmma::mem_row_major);
#pragma unroll
            for (int e = 0; e < c.num_elements; ++e)
                c.x[e] += lrelu(acc[i][j].x[e]);
            wmma::store_matrix_sync(g_x + off, c, Dz, wmma::mem_row_major);
        }
}

__global__ void __launch_bounds__(256, 2) head_tc()
{
    extern __shared__ __align__(128) __half smh[];
    int n0 = blockIdx.x * 128, m0 = blockIdx.y * 128;
    FragC acc[2][4];
    gemm_h(g_th + (size_t)m0 * 2048, 2048,
           g_w1h + (size_t)n0 * 2048, 2048, 2048, acc, smh);

    int wm = (threadIdx.x >> 5) & 3, wn = threadIdx.x >> 7;
#pragma unroll
    for (int i = 0; i < 2; ++i)
#pragma unroll
        for (int j = 0; j < 4; ++j)
            wmma::store_matrix_sync(g_h1 + (size_t)(m0 + wm * 32 + i * 16) * 2048
                                         + n0 + wn * 64 + j * 16,
                                    acc[i][j], 2048, wmma::mem_row_major);
}

__global__ void __launch_bounds__(512) head_bias(const float* __restrict__ b1)
{
    int idx = blockIdx.x * 512 + threadIdx.x;
    g_h1[idx] = lrelu(g_h1[idx] + b1[idx & 2047]);
}

// ---------------- elementwise conversions ----------------
__global__ void __launch_bounds__(256) y1_to_half()
{
    size_t i = ((size_t)blockIdx.x * 256 + threadIdx.x) * 8;
    float4 a = *reinterpret_cast<const float4*>(g_y1 + i);
    float4 b = *reinterpret_cast<const float4*>(g_y1 + i + 4);
    __half2 h0 = __floats2half2_rn(lrelu(a.x), lrelu(a.y));
    __half2 h1 = __floats2half2_rn(lrelu(a.z), lrelu(a.w));
    __half2 h2 = __floats2half2_rn(lrelu(b.x), lrelu(b.y));
    __half2 h3 = __floats2half2_rn(lrelu(b.z), lrelu(b.w));
    uint4 o = make_uint4(*(uint32_t*)&h0, *(uint32_t*)&h1, *(uint32_t*)&h2, *(uint32_t*)&h3);
    *reinterpret_cast<uint4*>(g_y1h + i) = o;
}

__global__ void __launch_bounds__(256) x_to_half()
{
    size_t i = ((size_t)blockIdx.x * 256 + threadIdx.x) * 8;
    float4 a = *reinterpret_cast<const float4*>(g_x + i);
    float4 b = *reinterpret_cast<const float4*>(g_x + i + 4);
    __half2 h0 = __floats2half2_rn(a.x, a.y);
    __half2 h1 = __floats2half2_rn(a.z, a.w);
    __half2 h2 = __floats2half2_rn(b.x, b.y);
    __half2 h3 = __floats2half2_rn(b.z, b.w);
    uint4 o = make_uint4(*(uint32_t*)&h0, *(uint32_t*)&h1, *(uint32_t*)&h2, *(uint32_t*)&h3);
    *reinterpret_cast<uint4*>(g_xh + i) = o;
}

// ---------------- embedding + layernorm ----------------
__device__ __forceinline__ void blockReduce2(float& s1, float& s2) {
    __shared__ float buf[32];
    int lane = threadIdx.x & 31, warp = threadIdx.x >> 5;
#pragma unroll
    for (int o = 16; o; o >>= 1) {
        s1 += __shfl_xor_sync(0xffffffffu, s1, o);
        s2 += __shfl_xor_sync(0xffffffffu, s2, o);
    }
    if (lane == 0) { buf[warp] = s1; buf[16 + warp] = s2; }
    __syncthreads();
    float t1 = 0.f, t2 = 0.f;
#pragma unroll
    for (int w = 0; w < 8; ++w) { t1 += buf[w]; t2 += buf[16 + w]; }
    s1 = t1; s2 = t2;
}

__global__ void __launch_bounds__(256) embed_kernel(
    const int* __restrict__ fen, const int* __restrict__ move,
    const float* __restrict__ rank_emb, const float* __restrict__ file_emb,
    const float* __restrict__ fen_emb, const float* __restrict__ move_emb,
    const float* __restrict__ lng, const float* __restrict__ lnb,
    const float* __restrict__ abs_emb)
{
    int token = blockIdx.x;
    int b = token / Tz, t = token - b * Tz;
    int tid = threadIdx.x;
    float vals[4];

    if (t < 64) {
        int i1 = fen[b * 133 + t];
        int i2 = fen[b * 133 + 64 + t];
        int r = t >> 3, f = t & 7;
#pragma unroll
        for (int c = 0; c < 4; ++c) {
            int d = tid + c * 256;
            vals[c] = 0.5f * (fen_emb[i1 * Dz + d] + fen_emb[i2 * Dz + d]
                              + rank_emb[r * Dz + d] + file_emb[f * Dz + d])
                      + abs_emb[t * Dz + d];
        }
    } else if (t < 69) {
        int i1 = fen[b * 133 + 128 + (t - 64)];
#pragma unroll
        for (int c = 0; c < 4; ++c) {
            int d = tid + c * 256;
            vals[c] = fen_emb[i1 * Dz + d] + abs_emb[t * Dz + d];
        }
    } else {
        int i = t - 69;
        int m = move[b * 2 + i];
        int r = m >> 3, f = m & 7;
#pragma unroll
        for (int c = 0; c < 4; ++c) {
            int d = tid + c * 256;
            vals[c] = (rank_emb[r * Dz + d] + file_emb[f * Dz + d] + move_emb[i * Dz + d]) * 0.58f
                      + abs_emb[t * Dz + d];
        }
    }

    float s1 = 0.f, s2 = 0.f;
#pragma unroll
    for (int c = 0; c < 4; ++c) { s1 += vals[c]; s2 += vals[c] * vals[c]; }
    blockReduce2(s1, s2);
    float mean = s1 * (1.f / 1024.f);
    float var  = s2 * (1.f / 1024.f) - mean * mean;
    float inv  = rsqrtf(var + 1e-5f);

    float*  xp  = g_x  + (size_t)token * Dz;
    __half* xhp = g_xh + (size_t)token * Dz;
#pragma unroll
    for (int c = 0; c < 4; ++c) {
        int d = tid + c * 256;
        float y = (vals[c] - mean) * inv * lng[d] + lnb[d];
        xp[d]  = y;
        xhp[d] = __float2half(y);
    }
}

// ---------------- weight prep ----------------
__global__ void transposeW(const float* __restrict__ src, __half* __restrict__ dst, int K)
{
    __shared__ float tile[32][33];
    size_t mstride = (size_t)K * 128;
    src += blockIdx.z * mstride;
    dst += blockIdx.z * mstride;
    int k0 = blockIdx.x * 32, n0 = blockIdx.y * 32;
    for (int i = threadIdx.y; i < 32; i += 8)
        tile[i][threadIdx.x] = src[(size_t)(k0 + i) * 128 + n0 + threadIdx.x];
    __syncthreads();
    for (int i = threadIdx.y; i < 32; i += 8)
        dst[(size_t)(n0 + i) * K + k0 + threadIdx.x] = __float2half(tile[threadIdx.x][i]);
}

__global__ void __launch_bounds__(512) halfW1(const float* __restrict__ W1)
{
    int idx = blockIdx.x * 512 + threadIdx.x;
    g_w1h[idx] = __float2half(W1[idx]);
}

// ---------------- attention (SIMT fp32) ----------------
__global__ void __launch_bounds__(256) attn_kernel()
{
    int b = blockIdx.x, h = blockIdx.y;
    int tid = threadIdx.x;
    extern __shared__ float smf[];
    float* qs = smf;
    float* ks = qs + Tz * 128;
    float* vs = ks + Tz * 129;
    float* ps = vs + Tz * 128;

    const float* qb = g_q + ((size_t)b * Tz) * Dz + h * DHz;
    const float* kb = g_k + ((size_t)b * Tz) * Dz + h * DHz;
    const float* vb = g_v + ((size_t)b * Tz) * Dz + h * DHz;

    for (int i = tid; i < Tz * 128; i += 256) {
        int t = i >> 7, d = i & 127;
        qs[t * 128 + d] = qb[(size_t)t * Dz + d];
        ks[t * 129 + d] = kb[(size_t)t * Dz + d];
        vs[t * 128 + d] = vb[(size_t)t * Dz + d];
    }
    __syncthreads();

    const float inv_scale = 0.08838834764831845f;
    for (int idx = tid; idx < Tz * Tz; idx += 256) {
        int i = idx / Tz, j = idx - i * Tz;
        float s = 0.f;
#pragma unroll 8
        for (int dd = 0; dd < 128; ++dd)
            s = fmaf(qs[i * 128 + dd], ks[j * 129 + dd], s);
        ps[i * 72 + j] = s * inv_scale;
    }
    __syncthreads();

    int warp = tid >> 5, lane = tid & 31;
    for (int r = warp; r < Tz; r += 8) {
        float m = -1e30f;
        for (int j = lane; j < Tz; j += 32) m = fmaxf(m, ps[r * 72 + j]);
#pragma unroll
        for (int o = 16; o; o >>= 1) m = fmaxf(m, __shfl_xor_sync(0xffffffffu, m, o));
        float ssum = 0.f;
        for (int j = lane; j < Tz; j += 32) {
            float e = expf(ps[r * 72 + j] - m);
            ps[r * 72 + j] = e;
            ssum += e;
        }
#pragma unroll
        for (int o = 16; o; o >>= 1) ssum += __shfl_xor_sync(0xffffffffu, ssum, o);
        float inv = 1.f / ssum;
        for (int j = lane; j < Tz; j += 32) ps[r * 72 + j] *= inv;
    }
    __syncthreads();

    float*  xb  = g_x  + ((size_t)b * Tz) * Dz + h * DHz;
    __half* xhb = g_xh + ((size_t)b * Tz) * Dz + h * DHz;
    for (int idx = tid; idx < Tz * 128; idx += 256) {
        int i = idx >> 7, d = idx & 127;
        float a = 0.f;
#pragma unroll 8
        for (int j = 0; j < Tz; ++j)
            a = fmaf(ps[i * 72 + j], vs[j * 128 + d], a);
        float y = xb[(size_t)i * Dz + d] + a;
        xb[(size_t)i * Dz + d]  = y;
        xhb[(size_t)i * Dz + d] = __float2half(y);
    }
}

// ---------------- head: gather + LN over 2048 ----------------
__global__ void __launch_bounds__(256) gather_ln_kernel(const float* __restrict__ g,
                                                        const float* __restrict__ bb)
{
    int b = blockIdx.x, tid = threadIdx.x;
    const float* x69 = g_x + ((size_t)b * Tz + 69) * Dz;
    float vals[8];
#pragma unroll
    for (int c = 0; c < 8; ++c) vals[c] = x69[tid + c * 256];
    float s1 = 0.f, s2 = 0.f;
#pragma unroll
    for (int c = 0; c < 8; ++c) { s1 += vals[c]; s2 += vals[c] * vals[c]; }
    blockReduce2(s1, s2);
    float mean = s1 * (1.f / 2048.f);
    float var  = s2 * (1.f / 2048.f) - mean * mean;
    float inv  = rsqrtf(var + 1e-5f);
    __half* tp = g_th + (size_t)b * 2048;
#pragma unroll
    for (int c = 0; c < 8; ++c) {
        int k = tid + c * 256;
        tp[k] = __float2half((vals[c] - mean) * inv * g[k] + bb[k]);
    }
}

__global__ void __launch_bounds__(256) final_kernel(const float* __restrict__ W2,
                                                    const float* __restrict__ b2,
                                                    float* __restrict__ out)
{
    int b = blockIdx.x, tid = threadIdx.x;
    const float* hp = g_h1 + (size_t)b * 2048;
    float s = 0.f;
    for (int k = tid; k < 2048; k += 256) s = fmaf(hp[k], W2[k], s);
    float dummy = 0.f;
    blockReduce2(s, dummy);
    if (tid == 0) out[b] = 1.f / (1.f + expf(-(s + b2[0])));
}

// ---------------- launch ----------------
extern "C" void kernel_launch(void* const* d_in, const int* in_sizes, int n_in,
                              void* d_out, int out_size)
{
    const int*   fen      = (const int*)  d_in[0];
    const int*   move     = (const int*)  d_in[1];
    const float* rank_emb = (const float*)d_in[2];
    const float* file_emb = (const float*)d_in[3];
    const float* fen_emb  = (const float*)d_in[4];
    const float* move_emb = (const float*)d_in[5];
    const float* ln_emb_g = (const float*)d_in[6];
    const float* ln_emb_b = (const float*)d_in[7];
    const float* abs_emb  = (const float*)d_in[8];
    const float* qkvw     = (const float*)d_in[9];
    const float* ff1w     = (const float*)d_in[10];
    const float* ff2w     = (const float*)d_in[11];
    const float* ln_out_g = (const float*)d_in[12];
    const float* ln_out_b = (const float*)d_in[13];
    const float* W1       = (const float*)d_in[14];
    const float* b1       = (const float*)d_in[15];
    const float* W2       = (const float*)d_in[16];
    const float* b2       = (const float*)d_in[17];
    float* out = (float*)d_out;

    const int ATTN_SMEM = (Tz * 128 * 2 + Tz * 129 + Tz * 72) * (int)sizeof(float);
    cudaFuncSetAttribute(attn_kernel, cudaFuncAttributeMaxDynamicSharedMemorySize, ATTN_SMEM);
    cudaFuncSetAttribute(qkv_tc,  cudaFuncAttributeMaxDynamicSharedMemorySize, GSMH);
    cudaFuncSetAttribute(ff1_tc,  cudaFuncAttributeMaxDynamicSharedMemorySize, GSMH);
    cudaFuncSetAttribute(ff2_tc,  cudaFuncAttributeMaxDynamicSharedMemorySize, GSMH);
    cudaFuncSetAttribute(head_tc, cudaFuncAttributeMaxDynamicSharedMemorySize, GSMH);

    __half* qkvT; cudaGetSymbolAddress((void**)&qkvT, g_qkvTh);
    __half* ff1T; cudaGetSymbolAddress((void**)&ff1T, g_ff1Th);
    __half* ff2T; cudaGetSymbolAddress((void**)&ff2T, g_ff2Th);
    transposeW<<<dim3(4, 4, Lz * 3 * Hz), dim3(32, 8)>>>(qkvw, qkvT, 128);
    transposeW<<<dim3(32, 4, Lz * Hz), dim3(32, 8)>>>(ff1w, ff1T, 1024);
    transposeW<<<dim3(4, 4, Lz * Hz), dim3(32, 8)>>>(ff2w, ff2T, 128);
    halfW1<<<(2 * Dz * 2 * Dz) / 512, 512>>>(W1);

    embed_kernel<<<NTOK, 256>>>(fen, move, rank_emb, file_emb, fen_emb, move_emb,
                                ln_emb_g, ln_emb_b, abs_emb);

    const int CONV_BLOCKS = (int)(((size_t)NTOK * Dz) / (256 * 8));   // 72704
    for (int l = 0; l < Lz; ++l) {
        const __half* qkvT_l = qkvT + (size_t)l * 3 * Hz * DHz * DHz;
        const __half* ff1T_l = ff1T + (size_t)l * Hz * DHz * Dz;
        const __half* ff2T_l = ff2T + (size_t)l * Hz * DHz * DHz;
        qkv_tc<<<dim3(24, MTILES), 256, GSMH>>>(qkvT_l);
        attn_kernel<<<dim3(Bz, Hz), 256, ATTN_SMEM>>>();
        ff1_tc<<<dim3(8, MTILES), 256, GSMH>>>(ff1T_l);
        y1_to_half<<<CONV_BLOCKS, 256>>>();
        ff2_tc<<<dim3(8, MTILES), 256, GSMH>>>(ff2T_l);
        x_to_half<<<CONV_BLOCKS, 256>>>();
    }

    gather_ln_kernel<<<Bz, 256>>>(ln_out_g, ln_out_b);
    head_tc<<<dim3(16, 16), 256, GSMH>>>();
    head_bias<<<(Bz * 2048) / 512, 512>>>(b1);
    final_kernel<<<Bz, 256>>>(W2, b2, out);
}

// round 7
// speedup vs baseline: 5.3591x; 3.4146x over previous
#include <cuda_runtime.h>
#include <cuda_fp16.h>
#include <mma.h>
#include <math.h>
#include <stdint.h>

using namespace nvcuda;

// ---------------- problem constants ----------------
#define Bz   2048
#define Tz   71
#define Dz   1024
#define Hz   8
#define DHz  128
#define Lz   12
#define NTOK (Bz*Tz)            // 145408
#define MTILES (NTOK/128)       // 1136

// ---------------- device scratch ----------------
__device__ float  g_x  [NTOK*Dz];   // fp32 residual stream
__device__ __half g_xh [NTOK*Dz];   // half mirror (GEMM A operand)
__device__ __half g_qh [NTOK*Dz];
__device__ __half g_kh [NTOK*Dz];
__device__ __half g_vh [NTOK*Dz];
__device__ __half g_y1h[NTOK*Dz];   // lrelu(ff1) half
__device__ __half g_th [Bz*2*Dz];
__device__ float  g_h1 [Bz*2*Dz];
__device__ __half g_qkvTh[Lz*3*Hz*DHz*DHz];
__device__ __half g_ff1Th[Lz*Hz*DHz*Dz];
__device__ __half g_ff2Th[Lz*Hz*DHz*DHz];
__device__ __half g_w1h[2*Dz*2*Dz];

__device__ __forceinline__ float lrelu(float x) { return x > 0.f ? x : 0.2f * x; }

// ---------------- cp.async helpers ----------------
__device__ __forceinline__ void cpa16(uint32_t s, const void* g) {
    asm volatile("cp.async.cg.shared.global [%0], [%1], 16;" :: "r"(s), "l"(g));
}
#define CPA_COMMIT() asm volatile("cp.async.commit_group;" ::: "memory")
#define CPA_WAIT1()  asm volatile("cp.async.wait_group 1;" ::: "memory")
#define CPA_WAIT0()  asm volatile("cp.async.wait_group 0;" ::: "memory")

// ---------------- wmma types ----------------
using FragA  = wmma::fragment<wmma::matrix_a, 16, 16, 16, __half, wmma::row_major>;
using FragB  = wmma::fragment<wmma::matrix_b, 16, 16, 16, __half, wmma::col_major>;
using FragBR = wmma::fragment<wmma::matrix_b, 16, 16, 16, __half, wmma::row_major>;
using FragC  = wmma::fragment<wmma::accumulator, 16, 16, 16, float>;

#define LDSH  72
#define MBUFH (128 * LDSH)
#define GSMH  (2 * 2 * MBUFH * 2)    // 73728 bytes
#define STGLD 132                    // fp32 staging stride (128x132x4 = 67584 <= GSMH)

// A: row-major [128 x K] half, B: K-contiguous [128n x K] half => C = A @ B^T
__device__ __forceinline__ void gemm_h(const __half* __restrict__ A, int lda,
                                       const __half* __restrict__ B, int ldb,
                                       int K, FragC (&acc)[2][4], __half* sm)
{
    const int tid = threadIdx.x;
    const int warp = tid >> 5;
    const int wm = warp & 3;
    const int wn = warp >> 2;
    const uint32_t smu = (uint32_t)__cvta_generic_to_shared(sm);

#pragma unroll
    for (int i = 0; i < 2; ++i)
#pragma unroll
        for (int j = 0; j < 4; ++j)
            wmma::fill_fragment(acc[i][j], 0.f);

    const int nch = K / 64;

    auto issue = [&](int c, int buf) {
        const int kk = c * 64;
        const uint32_t base = smu + (uint32_t)buf * (2u * MBUFH * 2u);
#pragma unroll
        for (int it = 0; it < 4; ++it) {
            int idx = tid + it * 256;
            int row = idx >> 3, seg = idx & 7;
            cpa16(base + (uint32_t)(row * LDSH * 2 + seg * 16),
                  A + (size_t)row * lda + kk + seg * 8);
        }
#pragma unroll
        for (int it = 0; it < 4; ++it) {
            int idx = tid + it * 256;
            int row = idx >> 3, seg = idx & 7;
            cpa16(base + (uint32_t)(MBUFH * 2) + (uint32_t)(row * LDSH * 2 + seg * 16),
                  B + (size_t)row * ldb + kk + seg * 8);
        }
        CPA_COMMIT();
    };

    issue(0, 0);
    for (int c = 0; c < nch; ++c) {
        if (c + 1 < nch) { issue(c + 1, (c + 1) & 1); CPA_WAIT1(); }
        else             { CPA_WAIT0(); }
        __syncthreads();
        __half* As = sm + (c & 1) * 2 * MBUFH;
        __half* Bs = As + MBUFH;
#pragma unroll
        for (int ks = 0; ks < 4; ++ks) {
            FragA af[2];
            wmma::load_matrix_sync(af[0], As + (wm * 32) * LDSH + ks * 16, LDSH);
            wmma::load_matrix_sync(af[1], As + (wm * 32 + 16) * LDSH + ks * 16, LDSH);
#pragma unroll
            for (int j = 0; j < 4; ++j) {
                FragB bf;
                wmma::load_matrix_sync(bf, Bs + (wn * 64 + j * 16) * LDSH + ks * 16, LDSH);
                wmma::mma_sync(acc[0][j], af[0], bf, acc[0][j]);
                wmma::mma_sync(acc[1][j], af[1], bf, acc[1][j]);
            }
        }
        __syncthreads();
    }
}

// stage 8 acc frags to fp32 smem (stride STGLD); caller then converts
__device__ __forceinline__ void stage_acc(FragC (&acc)[2][4], float* stage) {
    int wm = (threadIdx.x >> 5) & 3, wn = threadIdx.x >> 7;
#pragma unroll
    for (int i = 0; i < 2; ++i)
#pragma unroll
        for (int j = 0; j < 4; ++j)
            wmma::store_matrix_sync(stage + (wm * 32 + i * 16) * STGLD + wn * 64 + j * 16,
                                    acc[i][j], STGLD, wmma::mem_row_major);
    __syncthreads();
}

__device__ __forceinline__ uint4 f8_to_h8(float4 a, float4 b, bool relu) {
    if (relu) {
        a.x = lrelu(a.x); a.y = lrelu(a.y); a.z = lrelu(a.z); a.w = lrelu(a.w);
        b.x = lrelu(b.x); b.y = lrelu(b.y); b.z = lrelu(b.z); b.w = lrelu(b.w);
    }
    __half2 h0 = __floats2half2_rn(a.x, a.y), h1 = __floats2half2_rn(a.z, a.w);
    __half2 h2 = __floats2half2_rn(b.x, b.y), h3 = __floats2half2_rn(b.z, b.w);
    return make_uint4(*(uint32_t*)&h0, *(uint32_t*)&h1, *(uint32_t*)&h2, *(uint32_t*)&h3);
}

// ---------------- GEMM kernels ----------------
__global__ void __launch_bounds__(256, 2) qkv_tc(const __half* __restrict__ qkvT_l)
{
    extern __shared__ __align__(128) __half smh[];
    int sh = blockIdx.x, s = sh >> 3, h = sh & 7;
    int m0 = blockIdx.y * 128;
    FragC acc[2][4];
    gemm_h(g_xh + (size_t)m0 * Dz + h * DHz, Dz,
           qkvT_l + (size_t)sh * (DHz * DHz), DHz, DHz, acc, smh);

    float* stage = (float*)smh;
    stage_acc(acc, stage);
    __half* out = (s == 0) ? g_qh : (s == 1) ? g_kh : g_vh;
#pragma unroll
    for (int it = 0; it < 8; ++it) {
        int idx = threadIdx.x + it * 256;
        int row = idx >> 4, sg = idx & 15;
        float4 a = *(float4*)(stage + row * STGLD + sg * 8);
        float4 b = *(float4*)(stage + row * STGLD + sg * 8 + 4);
        *(uint4*)(out + (size_t)(m0 + row) * Dz + h * DHz + sg * 8) = f8_to_h8(a, b, false);
    }
}

__global__ void __launch_bounds__(256, 2) ff1_tc(const __half* __restrict__ ff1T_l)
{
    extern __shared__ __align__(128) __half smh[];
    int n0 = blockIdx.x * 128, m0 = blockIdx.y * 128;
    FragC acc[2][4];
    gemm_h(g_xh + (size_t)m0 * Dz, Dz,
           ff1T_l + (size_t)n0 * Dz, Dz, Dz, acc, smh);

    float* stage = (float*)smh;
    stage_acc(acc, stage);
#pragma unroll
    for (int it = 0; it < 8; ++it) {
        int idx = threadIdx.x + it * 256;
        int row = idx >> 4, sg = idx & 15;
        float4 a = *(float4*)(stage + row * STGLD + sg * 8);
        float4 b = *(float4*)(stage + row * STGLD + sg * 8 + 4);
        *(uint4*)(g_y1h + (size_t)(m0 + row) * Dz + n0 + sg * 8) = f8_to_h8(a, b, true);
    }
}

__global__ void __launch_bounds__(256, 2) ff2_tc(const __half* __restrict__ ff2T_l)
{
    extern __shared__ __align__(128) __half smh[];
    int h = blockIdx.x, m0 = blockIdx.y * 128;
    FragC acc[2][4];
    gemm_h(g_y1h + (size_t)m0 * Dz + h * DHz, Dz,
           ff2T_l + (size_t)h * (DHz * DHz), DHz, DHz, acc, smh);

    int wm = (threadIdx.x >> 5) & 3, wn = threadIdx.x >> 7;
    float* stage = (float*)smh;
#pragma unroll
    for (int i = 0; i < 2; ++i)
#pragma unroll
        for (int j = 0; j < 4; ++j) {
            size_t off = (size_t)(m0 + wm * 32 + i * 16) * Dz + h * DHz + wn * 64 + j * 16;
            FragC c;
            wmma::load_matrix_sync(c, g_x + off, Dz, wmma::mem_row_major);
#pragma unroll
            for (int e = 0; e < c.num_elements; ++e)
                c.x[e] += lrelu(acc[i][j].x[e]);
            wmma::store_matrix_sync(g_x + off, c, Dz, wmma::mem_row_major);
            wmma::store_matrix_sync(stage + (wm * 32 + i * 16) * STGLD + wn * 64 + j * 16,
                                    c, STGLD, wmma::mem_row_major);
        }
    __syncthreads();
#pragma unroll
    for (int it = 0; it < 8; ++it) {
        int idx = threadIdx.x + it * 256;
        int row = idx >> 4, sg = idx & 15;
        float4 a = *(float4*)(stage + row * STGLD + sg * 8);
        float4 b = *(float4*)(stage + row * STGLD + sg * 8 + 4);
        *(uint4*)(g_xh + (size_t)(m0 + row) * Dz + h * DHz + sg * 8) = f8_to_h8(a, b, false);
    }
}

__global__ void __launch_bounds__(256, 2) head_tc(const float* __restrict__ b1)
{
    extern __shared__ __align__(128) __half smh[];
    int n0 = blockIdx.x * 128, m0 = blockIdx.y * 128;
    FragC acc[2][4];
    gemm_h(g_th + (size_t)m0 * 2048, 2048,
           g_w1h + (size_t)n0 * 2048, 2048, 2048, acc, smh);

    float* stage = (float*)smh;
    stage_acc(acc, stage);
#pragma unroll
    for (int it = 0; it < 16; ++it) {
        int idx = threadIdx.x + it * 256;      // 128 rows x 32 segs of 4
        int row = idx >> 5, sg = idx & 31;
        float4 a = *(float4*)(stage + row * STGLD + sg * 4);
        int col = n0 + sg * 4;
        a.x = lrelu(a.x + b1[col]);     a.y = lrelu(a.y + b1[col + 1]);
        a.z = lrelu(a.z + b1[col + 2]); a.w = lrelu(a.w + b1[col + 3]);
        *(float4*)(g_h1 + (size_t)(m0 + row) * 2048 + col) = a;
    }
}

// ---------------- attention via wmma fp16 ----------------
// smem: ks(80x136h) vs(80x136h) qs(80x136h) S(80x84f) P(80x88h); Ost overlays qs+S
#define ALD 136
#define SLD 84
#define PLD 88
#define OLD 132
#define ATTN_SMEM2 (3*80*ALD*2 + 80*SLD*4 + 80*PLD*2)   // 106240

__global__ void __launch_bounds__(256, 2) attn_wmma()
{
    extern __shared__ __align__(16) char smc[];
    __half* ks = (__half*)smc;
    __half* vs = ks + 80 * ALD;
    __half* qs = vs + 80 * ALD;
    float*  S  = (float*)(qs + 80 * ALD);
    __half* P  = (__half*)(S + 80 * SLD);
    float*  Ost = (float*)(smc + 2 * 80 * ALD * 2);   // overlays qs..S (free after P)

    int b = blockIdx.x, h = blockIdx.y;
    int tid = threadIdx.x, warp = tid >> 5, lane = tid & 31;

    const __half* qb = g_qh + ((size_t)b * Tz) * Dz + h * DHz;
    const __half* kb = g_kh + ((size_t)b * Tz) * Dz + h * DHz;
    const __half* vb = g_vh + ((size_t)b * Tz) * Dz + h * DHz;

    for (int idx = tid; idx < Tz * 16; idx += 256) {
        int t = idx >> 4, sg = idx & 15;
        *(uint4*)(qs + t * ALD + sg * 8) = *(const uint4*)(qb + (size_t)t * Dz + sg * 8);
        *(uint4*)(ks + t * ALD + sg * 8) = *(const uint4*)(kb + (size_t)t * Dz + sg * 8);
        *(uint4*)(vs + t * ALD + sg * 8) = *(const uint4*)(vb + (size_t)t * Dz + sg * 8);
    }
    uint4 z4 = make_uint4(0, 0, 0, 0);
    for (int idx = tid; idx < 9 * 16; idx += 256) {
        int t = 71 + (idx >> 4), sg = idx & 15;
        *(uint4*)(qs + t * ALD + sg * 8) = z4;
        *(uint4*)(ks + t * ALD + sg * 8) = z4;
        *(uint4*)(vs + t * ALD + sg * 8) = z4;
    }
    __syncthreads();

    // S = q @ k^T  (25 tiles of 16x16, K=128)
    for (int t = warp; t < 25; t += 8) {
        int mi = t / 5, nj = t % 5;
        FragC acc;
        wmma::fill_fragment(acc, 0.f);
#pragma unroll
        for (int k = 0; k < 8; ++k) {
            FragA a; FragB bf;
            wmma::load_matrix_sync(a,  qs + mi * 16 * ALD + k * 16, ALD);
            wmma::load_matrix_sync(bf, ks + nj * 16 * ALD + k * 16, ALD);
            wmma::mma_sync(acc, a, bf, acc);
        }
        wmma::store_matrix_sync(S + mi * 16 * SLD + nj * 16, acc, SLD, wmma::mem_row_major);
    }
    __syncthreads();

    // softmax rows 0..70 over cols 0..70 (scaled); P half
    const float inv_scale = 0.08838834764831845f;
    for (int r = warp; r < Tz; r += 8) {
        float mx = -1e30f;
        for (int j = lane; j < Tz; j += 32) mx = fmaxf(mx, S[r * SLD + j] * inv_scale);
#pragma unroll
        for (int o = 16; o; o >>= 1) mx = fmaxf(mx, __shfl_xor_sync(0xffffffffu, mx, o));
        float sum = 0.f;
        for (int j = lane; j < Tz; j += 32) {
            float e = expf(S[r * SLD + j] * inv_scale - mx);
            S[r * SLD + j] = e;
            sum += e;
        }
#pragma unroll
        for (int o = 16; o; o >>= 1) sum += __shfl_xor_sync(0xffffffffu, sum, o);
        float inv = 1.f / sum;
        for (int j = lane; j < 80; j += 32)
            P[r * PLD + j] = __float2half(j < Tz ? S[r * SLD + j] * inv : 0.f);
    }
    for (int idx = tid; idx < 9 * PLD; idx += 256)
        P[(Tz + idx / PLD) * PLD + (idx % PLD)] = __float2half(0.f);
    __syncthreads();

    // O = P @ V  (warp w owns n-tile w; 5 m-tiles, K=80)
    FragBR bfr[5];
#pragma unroll
    for (int k = 0; k < 5; ++k)
        wmma::load_matrix_sync(bfr[k], vs + k * 16 * ALD + warp * 16, ALD);
#pragma unroll
    for (int m = 0; m < 5; ++m) {
        FragC acc;
        wmma::fill_fragment(acc, 0.f);
#pragma unroll
        for (int k = 0; k < 5; ++k) {
            FragA a;
            wmma::load_matrix_sync(a, P + m * 16 * PLD + k * 16, PLD);
            wmma::mma_sync(acc, a, bfr[k], acc);
        }
        wmma::store_matrix_sync(Ost + m * 16 * OLD + warp * 16, acc, OLD, wmma::mem_row_major);
    }
    __syncthreads();

    // residual: x += O ; write fp32 + half
    float*  xb  = g_x  + ((size_t)b * Tz) * Dz + h * DHz;
    __half* xhb = g_xh + ((size_t)b * Tz) * Dz + h * DHz;
    for (int idx = tid; idx < Tz * 32; idx += 256) {
        int r = idx >> 5, sg = idx & 31;
        float4 o = *(float4*)(Ost + r * OLD + sg * 4);
        float4 x = *(float4*)(xb + (size_t)r * Dz + sg * 4);
        x.x += o.x; x.y += o.y; x.z += o.z; x.w += o.w;
        *(float4*)(xb + (size_t)r * Dz + sg * 4) = x;
        __half2 h0 = __floats2half2_rn(x.x, x.y), h1 = __floats2half2_rn(x.z, x.w);
        uint2 u = make_uint2(*(uint32_t*)&h0, *(uint32_t*)&h1);
        *(uint2*)(xhb + (size_t)r * Dz + sg * 4) = u;
    }
}

// ---------------- embedding + layernorm ----------------
__device__ __forceinline__ void blockReduce2(float& s1, float& s2) {
    __shared__ float buf[32];
    int lane = threadIdx.x & 31, warp = threadIdx.x >> 5;
#pragma unroll
    for (int o = 16; o; o >>= 1) {
        s1 += __shfl_xor_sync(0xffffffffu, s1, o);
        s2 += __shfl_xor_sync(0xffffffffu, s2, o);
    }
    if (lane == 0) { buf[warp] = s1; buf[16 + warp] = s2; }
    __syncthreads();
    float t1 = 0.f, t2 = 0.f;
#pragma unroll
    for (int w = 0; w < 8; ++w) { t1 += buf[w]; t2 += buf[16 + w]; }
    s1 = t1; s2 = t2;
}

__global__ void __launch_bounds__(256) embed_kernel(
    const int* __restrict__ fen, const int* __restrict__ move,
    const float* __restrict__ rank_emb, const float* __restrict__ file_emb,
    const float* __restrict__ fen_emb, const float* __restrict__ move_emb,
    const float* __restrict__ lng, const float* __restrict__ lnb,
    const float* __restrict__ abs_emb)
{
    int token = blockIdx.x;
    int b = token / Tz, t = token - b * Tz;
    int tid = threadIdx.x;
    float vals[4];

    if (t < 64) {
        int i1 = fen[b * 133 + t];
        int i2 = fen[b * 133 + 64 + t];
        int r = t >> 3, f = t & 7;
#pragma unroll
        for (int c = 0; c < 4; ++c) {
            int d = tid + c * 256;
            vals[c] = 0.5f * (fen_emb[i1 * Dz + d] + fen_emb[i2 * Dz + d]
                              + rank_emb[r * Dz + d] + file_emb[f * Dz + d])
                      + abs_emb[t * Dz + d];
        }
    } else if (t < 69) {
        int i1 = fen[b * 133 + 128 + (t - 64)];
#pragma unroll
        for (int c = 0; c < 4; ++c) {
            int d = tid + c * 256;
            vals[c] = fen_emb[i1 * Dz + d] + abs_emb[t * Dz + d];
        }
    } else {
        int i = t - 69;
        int m = move[b * 2 + i];
        int r = m >> 3, f = m & 7;
#pragma unroll
        for (int c = 0; c < 4; ++c) {
            int d = tid + c * 256;
            vals[c] = (rank_emb[r * Dz + d] + file_emb[f * Dz + d] + move_emb[i * Dz + d]) * 0.58f
                      + abs_emb[t * Dz + d];
        }
    }

    float s1 = 0.f, s2 = 0.f;
#pragma unroll
    for (int c = 0; c < 4; ++c) { s1 += vals[c]; s2 += vals[c] * vals[c]; }
    blockReduce2(s1, s2);
    float mean = s1 * (1.f / 1024.f);
    float var  = s2 * (1.f / 1024.f) - mean * mean;
    float inv  = rsqrtf(var + 1e-5f);

    float*  xp  = g_x  + (size_t)token * Dz;
    __half* xhp = g_xh + (size_t)token * Dz;
#pragma unroll
    for (int c = 0; c < 4; ++c) {
        int d = tid + c * 256;
        float y = (vals[c] - mean) * inv * lng[d] + lnb[d];
        xp[d]  = y;
        xhp[d] = __float2half(y);
    }
}

// ---------------- weight prep ----------------
__global__ void transposeW(const float* __restrict__ src, __half* __restrict__ dst, int K)
{
    __shared__ float tile[32][33];
    size_t mstride = (size_t)K * 128;
    src += blockIdx.z * mstride;
    dst += blockIdx.z * mstride;
    int k0 = blockIdx.x * 32, n0 = blockIdx.y * 32;
    for (int i = threadIdx.y; i < 32; i += 8)
        tile[i][threadIdx.x] = src[(size_t)(k0 + i) * 128 + n0 + threadIdx.x];
    __syncthreads();
    for (int i = threadIdx.y; i < 32; i += 8)
        dst[(size_t)(n0 + i) * K + k0 + threadIdx.x] = __float2half(tile[threadIdx.x][i]);
}

__global__ void __launch_bounds__(512) halfW1(const float* __restrict__ W1)
{
    int idx = blockIdx.x * 512 + threadIdx.x;
    g_w1h[idx] = __float2half(W1[idx]);
}

// ---------------- head: gather + LN over 2048 ----------------
__global__ void __launch_bounds__(256) gather_ln_kernel(const float* __restrict__ g,
                                                        const float* __restrict__ bb)
{
    int b = blockIdx.x, tid = threadIdx.x;
    const float* x69 = g_x + ((size_t)b * Tz + 69) * Dz;
    float vals[8];
#pragma unroll
    for (int c = 0; c < 8; ++c) vals[c] = x69[tid + c * 256];
    float s1 = 0.f, s2 = 0.f;
#pragma unroll
    for (int c = 0; c < 8; ++c) { s1 += vals[c]; s2 += vals[c] * vals[c]; }
    blockReduce2(s1, s2);
    float mean = s1 * (1.f / 2048.f);
    float var  = s2 * (1.f / 2048.f) - mean * mean;
    float inv  = rsqrtf(var + 1e-5f);
    __half* tp = g_th + (size_t)b * 2048;
#pragma unroll
    for (int c = 0; c < 8; ++c) {
        int k = tid + c * 256;
        tp[k] = __float2half((vals[c] - mean) * inv * g[k] + bb[k]);
    }
}

__global__ void __launch_bounds__(256) final_kernel(const float* __restrict__ W2,
                                                    const float* __restrict__ b2,
                                                    float* __restrict__ out)
{
    int b = blockIdx.x, tid = threadIdx.x;
    const float* hp = g_h1 + (size_t)b * 2048;
    float s = 0.f;
    for (int k = tid; k < 2048; k += 256) s = fmaf(hp[k], W2[k], s);
    float dummy = 0.f;
    blockReduce2(s, dummy);
    if (tid == 0) out[b] = 1.f / (1.f + expf(-(s + b2[0])));
}

// ---------------- launch ----------------
extern "C" void kernel_launch(void* const* d_in, const int* in_sizes, int n_in,
                              void* d_out, int out_size)
{
    const int*   fen      = (const int*)  d_in[0];
    const int*   move     = (const int*)  d_in[1];
    const float* rank_emb = (const float*)d_in[2];
    const float* file_emb = (const float*)d_in[3];
    const float* fen_emb  = (const float*)d_in[4];
    const float* move_emb = (const float*)d_in[5];
    const float* ln_emb_g = (const float*)d_in[6];
    const float* ln_emb_b = (const float*)d_in[7];
    const float* abs_emb  = (const float*)d_in[8];
    const float* qkvw     = (const float*)d_in[9];
    const float* ff1w     = (const float*)d_in[10];
    const float* ff2w     = (const float*)d_in[11];
    const float* ln_out_g = (const float*)d_in[12];
    const float* ln_out_b = (const float*)d_in[13];
    const float* W1       = (const float*)d_in[14];
    const float* b1       = (const float*)d_in[15];
    const float* W2       = (const float*)d_in[16];
    const float* b2       = (const float*)d_in[17];
    float* out = (float*)d_out;

    cudaFuncSetAttribute(attn_wmma, cudaFuncAttributeMaxDynamicSharedMemorySize, ATTN_SMEM2);
    cudaFuncSetAttribute(qkv_tc,  cudaFuncAttributeMaxDynamicSharedMemorySize, GSMH);
    cudaFuncSetAttribute(ff1_tc,  cudaFuncAttributeMaxDynamicSharedMemorySize, GSMH);
    cudaFuncSetAttribute(ff2_tc,  cudaFuncAttributeMaxDynamicSharedMemorySize, GSMH);
    cudaFuncSetAttribute(head_tc, cudaFuncAttributeMaxDynamicSharedMemorySize, GSMH);

    __half* qkvT; cudaGetSymbolAddress((void**)&qkvT, g_qkvTh);
    __half* ff1T; cudaGetSymbolAddress((void**)&ff1T, g_ff1Th);
    __half* ff2T; cudaGetSymbolAddress((void**)&ff2T, g_ff2Th);
    transposeW<<<dim3(4, 4, Lz * 3 * Hz), dim3(32, 8)>>>(qkvw, qkvT, 128);
    transposeW<<<dim3(32, 4, Lz * Hz), dim3(32, 8)>>>(ff1w, ff1T, 1024);
    transposeW<<<dim3(4, 4, Lz * Hz), dim3(32, 8)>>>(ff2w, ff2T, 128);
    halfW1<<<(2 * Dz * 2 * Dz) / 512, 512>>>(W1);

    embed_kernel<<<NTOK, 256>>>(fen, move, rank_emb, file_emb, fen_emb, move_emb,
                                ln_emb_g, ln_emb_b, abs_emb);

    for (int l = 0; l < Lz; ++l) {
        const __half* qkvT_l = qkvT + (size_t)l * 3 * Hz * DHz * DHz;
        const __half* ff1T_l = ff1T + (size_t)l * Hz * DHz * Dz;
        const __half* ff2T_l = ff2T + (size_t)l * Hz * DHz * DHz;
        qkv_tc<<<dim3(24, MTILES), 256, GSMH>>>(qkvT_l);
        attn_wmma<<<dim3(Bz, Hz), 256, ATTN_SMEM2>>>();
        ff1_tc<<<dim3(8, MTILES), 256, GSMH>>>(ff1T_l);
        ff2_tc<<<dim3(8, MTILES), 256, GSMH>>>(ff2T_l);
    }

    gather_ln_kernel<<<Bz, 256>>>(ln_out_g, ln_out_b);
    head_tc<<<dim3(16, 16), 256, GSMH>>>(b1);
    final_kernel<<<Bz, 256>>>(W2, b2, out);
}